// round 2
// baseline (speedup 1.0000x reference)
#include <cuda_runtime.h>
#include <cuda_bf16.h>
#include <cstdint>

// ---------------------------------------------------------------------------
// MADPSNet: per-agent expert-selected MLP chain.
//   Only the selected expert per agent is observable in the output, so we
//   compute 4 per-agent GEMMs instead of all-E expert GEMMs (8x fewer FLOPs
//   than the reference einsum formulation).
//
//   L1: y1 = relu(in  @ Ws1[e_s] + bs1[e_s])   [2048,256]x[256,512]
//   L2: y2 = relu(y1  @ Ws2[e_s] + bs2[e_s])   [2048,512]x[512,256]
//   L3: y3 = relu(y2  @ Wd1[e_d] + bd1[e_d])   [2048,256]x[256,512]
//   L4: out =      y3 @ Wd2[e_d] + bd2[e_d]    [2048,512]x[512,128]
//
// GEMM: 128x128 block tile, BK=16, 256 threads, 8x8 microtile per thread,
// accumulated as 8x4 packed f32x2 via fma.rn.f32x2 (full-rate fp32 on
// Blackwell; scalar 3-reg FFMA is half-rate).
// ---------------------------------------------------------------------------

#define NUM_AGENTS 8
#define BATCH      2048

// Scratch (allocation-free rule: __device__ globals)
__device__ float g_y1[NUM_AGENTS * BATCH * 512];
__device__ float g_y2[NUM_AGENTS * BATCH * 256];
__device__ float g_y3[NUM_AGENTS * BATCH * 512];

typedef unsigned long long u64;

__device__ __forceinline__ u64 pack2(float lo, float hi) {
    u64 r;
    asm("mov.b64 %0, {%1, %2};" : "=l"(r) : "f"(lo), "f"(hi));
    return r;
}
__device__ __forceinline__ u64 fma2(u64 a, u64 b, u64 c) {
    u64 d;
    asm("fma.rn.f32x2 %0, %1, %2, %3;" : "=l"(d) : "l"(a), "l"(b), "l"(c));
    return d;
}
__device__ __forceinline__ float2 unpack2(u64 v) {
    float2 f;
    asm("mov.b64 {%0, %1}, %2;" : "=f"(f.x), "=f"(f.y) : "l"(v));
    return f;
}

// C[ag] = act(In[ag] @ W[sel[ag]] + b[sel[ag]])
// In:  [NUM_AGENTS, BATCH, K]   W: [E, K, N]   b: [E, N]   C: [NUM_AGENTS, BATCH, N]
template <int K, int N, bool RELU>
__global__ void __launch_bounds__(256)
gemm_sel_kernel(const float* __restrict__ In,
                const float* __restrict__ Wall,
                const float* __restrict__ Ball,
                float* __restrict__ Out,
                const int* __restrict__ sel)
{
    const int ag = blockIdx.z;
    int e = sel[ag];
    e = e < 0 ? 0 : (e > 7 ? 7 : e);   // crash insurance on index dtype

    const float* Ap = In   + (size_t)ag * BATCH * K;
    const float* Wp = Wall + (size_t)e  * K * N;
    const float* bp = Ball + (size_t)e  * N;
    float*       Cp = Out  + (size_t)ag * BATCH * N;

    const int bm = blockIdx.y * 128;
    const int bn = blockIdx.x * 128;

    __shared__ float As[16][128];   // [k][m]
    __shared__ float Ws[16][128];   // [k][n]

    const int tid = threadIdx.x;
    const int tx  = tid & 15;       // column group (8 cols each)
    const int ty  = tid >> 4;       // row group    (8 rows each)

    u64 acc[8][4];
#pragma unroll
    for (int i = 0; i < 8; i++)
#pragma unroll
        for (int j = 0; j < 4; j++) acc[i][j] = 0ull;

    for (int k0 = 0; k0 < K; k0 += 16) {
        // --- load A tile (128 rows x 16 k) : 512 float4, 2 per thread, transpose to As[k][m]
#pragma unroll
        for (int l = 0; l < 2; l++) {
            int fid = tid * 2 + l;
            int m   = fid >> 2;
            int ks  = fid & 3;
            float4 v = *(const float4*)(Ap + (size_t)(bm + m) * K + k0 + ks * 4);
            As[ks * 4 + 0][m] = v.x;
            As[ks * 4 + 1][m] = v.y;
            As[ks * 4 + 2][m] = v.z;
            As[ks * 4 + 3][m] = v.w;
        }
        // --- load W tile (16 k x 128 n) : 512 float4, 2 per thread
#pragma unroll
        for (int l = 0; l < 2; l++) {
            int fid = tid * 2 + l;
            int kk  = fid >> 5;
            int ns  = fid & 31;
            *(float4*)&Ws[kk][ns * 4] =
                *(const float4*)(Wp + (size_t)(k0 + kk) * N + bn + ns * 4);
        }
        __syncthreads();

#pragma unroll
        for (int kk = 0; kk < 16; kk++) {
            // b fragment: 8 consecutive floats = 4 packed f32x2 (two LDS.128)
            ulonglong2 w01 = *(const ulonglong2*)&Ws[kk][tx * 8];
            ulonglong2 w23 = *(const ulonglong2*)(&Ws[kk][tx * 8] + 4);
            u64 b2[4] = {w01.x, w01.y, w23.x, w23.y};
            // a fragment: 8 floats (two LDS.128), splat each into both lanes
            float4 a0 = *(const float4*)&As[kk][ty * 8];
            float4 a1 = *(const float4*)(&As[kk][ty * 8] + 4);
            float av[8] = {a0.x, a0.y, a0.z, a0.w, a1.x, a1.y, a1.z, a1.w};
#pragma unroll
            for (int i = 0; i < 8; i++) {
                u64 a2 = pack2(av[i], av[i]);
#pragma unroll
                for (int j = 0; j < 4; j++)
                    acc[i][j] = fma2(a2, b2[j], acc[i][j]);
            }
        }
        __syncthreads();
    }

    // --- epilogue: bias + optional relu, float4 stores
    float bb[8];
#pragma unroll
    for (int j = 0; j < 8; j++) bb[j] = bp[bn + tx * 8 + j];

#pragma unroll
    for (int i = 0; i < 8; i++) {
        float o[8];
#pragma unroll
        for (int j = 0; j < 4; j++) {
            float2 f = unpack2(acc[i][j]);
            o[2 * j]     = f.x + bb[2 * j];
            o[2 * j + 1] = f.y + bb[2 * j + 1];
        }
        if (RELU) {
#pragma unroll
            for (int j = 0; j < 8; j++) o[j] = fmaxf(o[j], 0.0f);
        }
        float* crow = Cp + (size_t)(bm + ty * 8 + i) * N + bn + tx * 8;
        *(float4*)crow       = make_float4(o[0], o[1], o[2], o[3]);
        *((float4*)crow + 1) = make_float4(o[4], o[5], o[6], o[7]);
    }
}

extern "C" void kernel_launch(void* const* d_in, const int* in_sizes, int n_in,
                              void* d_out, int out_size)
{
    // metadata order == setup_inputs dict order:
    // 0 inputs [8,2048,256] f32
    // 1 laac_shallow [1,8] int
    // 2 laac_deep    [1,8] int
    // 3 Ws1 [8,256,512]  4 bs1 [8,512]
    // 5 Ws2 [8,512,256]  6 bs2 [8,256]
    // 7 Wd1 [8,256,512]  8 bd1 [8,512]
    // 9 Wd2 [8,512,128] 10 bd2 [8,128]
    const float* inputs = (const float*)d_in[0];
    const int*   sel_s  = (const int*)d_in[1];
    const int*   sel_d  = (const int*)d_in[2];
    const float* Ws1 = (const float*)d_in[3];
    const float* bs1 = (const float*)d_in[4];
    const float* Ws2 = (const float*)d_in[5];
    const float* bs2 = (const float*)d_in[6];
    const float* Wd1 = (const float*)d_in[7];
    const float* bd1 = (const float*)d_in[8];
    const float* Wd2 = (const float*)d_in[9];
    const float* bd2 = (const float*)d_in[10];
    float* out = (float*)d_out;

    void *p1, *p2, *p3;
    cudaGetSymbolAddress(&p1, g_y1);
    cudaGetSymbolAddress(&p2, g_y2);
    cudaGetSymbolAddress(&p3, g_y3);
    float* y1 = (float*)p1;
    float* y2 = (float*)p2;
    float* y3 = (float*)p3;

    dim3 blk(256);
    // L1: K=256, N=512
    gemm_sel_kernel<256, 512, true><<<dim3(4, 16, 8), blk>>>(inputs, Ws1, bs1, y1, sel_s);
    // L2: K=512, N=256
    gemm_sel_kernel<512, 256, true><<<dim3(2, 16, 8), blk>>>(y1, Ws2, bs2, y2, sel_s);
    // L3: K=256, N=512
    gemm_sel_kernel<256, 512, true><<<dim3(4, 16, 8), blk>>>(y2, Wd1, bd1, y3, sel_d);
    // L4: K=512, N=128, no relu
    gemm_sel_kernel<512, 128, false><<<dim3(1, 16, 8), blk>>>(y3, Wd2, bd2, out, sel_d);
}

// round 4
// speedup vs baseline: 2.0829x; 2.0829x over previous
#include <cuda_runtime.h>
#include <cuda_bf16.h>
#include <cstdint>

// ---------------------------------------------------------------------------
// MADPSNet via mma.sync bf16 (3-pass hi/lo error-compensated) GEMMs.
// tcgen05 is unavailable (harness compiles PTX at .target sm_100, not
// sm_100a), so we use the compute_80-compatible mma.sync path, which still
// runs on the Blackwell tensor pipe.
//
//   L1: y1 = relu(in @ Ws1[e_s] + bs1)   [2048,256]x[256,512]
//   L2: y2 = relu(y1 @ Ws2[e_s] + bs2)   [2048,512]x[512,256]
//   L3: y3 = relu(y2 @ Wd1[e_d] + bd1)   [2048,256]x[256,512]
//   L4: out =      y3 @ Wd2[e_d] + bd2   [2048,512]x[512,128]
//
// Precision: each fp32 operand x is split into bf16 hi + bf16 lo
// (~16 mantissa bits combined); 3 MMA passes (ah*bh + ah*bl + al*bh) into
// fp32 accumulators -> relative error ~1e-4, well under the 1e-3 gate.
// ---------------------------------------------------------------------------

#define NUM_AGENTS 8
#define BATCH      2048
typedef __nv_bfloat16 bf16;

// ---------------- scratch (__device__ globals; no allocation allowed) -----
__device__ float g_y1[NUM_AGENTS * BATCH * 512];
__device__ float g_y2[NUM_AGENTS * BATCH * 256];
__device__ float g_y3[NUM_AGENTS * BATCH * 512];

__device__ bf16 g_w1h[NUM_AGENTS * 512 * 256];
__device__ bf16 g_w1l[NUM_AGENTS * 512 * 256];
__device__ bf16 g_w2h[NUM_AGENTS * 256 * 512];
__device__ bf16 g_w2l[NUM_AGENTS * 256 * 512];
__device__ bf16 g_w3h[NUM_AGENTS * 512 * 256];
__device__ bf16 g_w3l[NUM_AGENTS * 512 * 256];
__device__ bf16 g_w4h[NUM_AGENTS * 128 * 512];
__device__ bf16 g_w4l[NUM_AGENTS * 128 * 512];

// ---------------- helpers --------------------------------------------------
__device__ __forceinline__ uint32_t smem_u32(const void* p) {
    uint32_t a;
    asm("{ .reg .u64 t; cvta.to.shared.u64 t, %1; cvt.u32.u64 %0, t; }" : "=r"(a) : "l"(p));
    return a;
}
__device__ __forceinline__ void ldsm4(uint32_t (&r)[4], uint32_t addr) {
    asm volatile("ldmatrix.sync.aligned.m8n8.x4.shared.b16 {%0,%1,%2,%3}, [%4];"
                 : "=r"(r[0]), "=r"(r[1]), "=r"(r[2]), "=r"(r[3]) : "r"(addr));
}
__device__ __forceinline__ void mma_bf16(float (&d)[4], const uint32_t (&a)[4],
                                         uint32_t b0, uint32_t b1) {
    asm volatile(
        "mma.sync.aligned.m16n8k16.row.col.f32.bf16.bf16.f32 "
        "{%0,%1,%2,%3}, {%4,%5,%6,%7}, {%8,%9}, {%0,%1,%2,%3};"
        : "+f"(d[0]), "+f"(d[1]), "+f"(d[2]), "+f"(d[3])
        : "r"(a[0]), "r"(a[1]), "r"(a[2]), "r"(a[3]), "r"(b0), "r"(b1));
}
// round-to-bf16, returned as fp32 (exact)
__device__ __forceinline__ float bfr(float x) {
    return __bfloat162float(__float2bfloat16_rn(x));
}
__device__ __forceinline__ uint32_t pack2bf(float a, float b) {
    __nv_bfloat162 t = __floats2bfloat162_rn(a, b);
    return *reinterpret_cast<uint32_t*>(&t);
}
// swizzled byte offset within a 128x32-bf16 tile (64B rows):
// 16B chunk index XORed with (row>>1)&3 -> any 8 consecutive rows at the same
// logical chunk hit 8 distinct bank groups (conflict-free ldmatrix phases).
__device__ __forceinline__ uint32_t swa(int row, int c16) {
    return (uint32_t)(row * 64 + (((c16) ^ ((row >> 1) & 3)) << 4));
}

// ---------------- prepass: transpose + bf16-split selected expert weights --
// W[E,K,N] fp32 -> Wt_hi/lo[agent][N,K] bf16
template <int K, int N>
__global__ void __launch_bounds__(256)
wprep_kernel(const float* __restrict__ Wall, const int* __restrict__ sel,
             bf16* __restrict__ WtH, bf16* __restrict__ WtL)
{
    __shared__ float ts[32][33];
    const int ag = blockIdx.z;
    int e = sel[ag]; e = e < 0 ? 0 : (e > 7 ? 7 : e);
    const float* Wp = Wall + (size_t)e * K * N;
    const int k0 = blockIdx.x * 32, n0 = blockIdx.y * 32;
    const int tx = threadIdx.x, ty = threadIdx.y;   // 32 x 8
#pragma unroll
    for (int i = 0; i < 4; i++)
        ts[ty + 8 * i][tx] = Wp[(size_t)(k0 + ty + 8 * i) * N + n0 + tx];
    __syncthreads();
    bf16* oh = WtH + (size_t)ag * N * K;
    bf16* ol = WtL + (size_t)ag * N * K;
#pragma unroll
    for (int i = 0; i < 4; i++) {
        int n = n0 + ty + 8 * i;
        int k = k0 + tx;
        float x = ts[tx][ty + 8 * i];
        float h = bfr(x);
        oh[(size_t)n * K + k] = __float2bfloat16_rn(h);       // exact
        ol[(size_t)n * K + k] = __float2bfloat16_rn(x - h);
    }
}

// ---------------- main GEMM: C[ag] = act(A[ag] @ Wt[ag]^T + b[sel[ag]]) ----
// A: [NUM_AGENTS, BATCH, K] fp32 (hi/lo split on load)
// Wt hi/lo: [ag, N, K] bf16 (K-major: "col" operand for mma row.col)
// CTA: 128x128 tile, 256 thr, 8 warps in 4x2 (warp tile 32m x 64n), BK=32,
// double-buffered smem: per buffer A_hi|A_lo|B_hi|B_lo, 8KB each.
template <int K, int N, bool RELU>
__global__ void __launch_bounds__(256)
gemm_mma_kernel(const float* __restrict__ In,
                const bf16* __restrict__ WtH,
                const bf16* __restrict__ WtL,
                const float* __restrict__ Ball,
                float* __restrict__ Out,
                const int* __restrict__ sel)
{
    extern __shared__ __align__(1024) char smem[];
    const uint32_t sb = smem_u32(smem);

    const int tid  = threadIdx.x;
    const int wid  = tid >> 5;
    const int lane = tid & 31;

    const int ag = blockIdx.z;
    int e = sel[ag]; e = e < 0 ? 0 : (e > 7 ? 7 : e);

    const float* Ap = In  + (size_t)ag * BATCH * K;
    const bf16*  BH = WtH + (size_t)ag * N * K;
    const bf16*  BL = WtL + (size_t)ag * N * K;
    const float* bp = Ball + (size_t)e * N;
    float*       Cp = Out + (size_t)ag * BATCH * N;

    const int bm = blockIdx.y * 128;
    const int bn = blockIdx.x * 128;

    // smem: [0..512) bias fp32, [1024..) two 32KB tile buffers
    if (tid < 128) ((float*)smem)[tid] = bp[bn + tid];

    const int m0 = (wid >> 1) * 32;   // warp row origin within tile
    const int n0 = (wid & 1) * 64;    // warp col origin within tile

    // per-thread ldmatrix base addresses (buffer 0, kstep 0)
    const int lrow = lane & 15;
    const int lqh  = lane >> 4;
    uint32_t aAb[2], aBb[4];
#pragma unroll
    for (int mt = 0; mt < 2; mt++)
        aAb[mt] = sb + 1024 + swa(m0 + mt * 16 + lrow, lqh);
#pragma unroll
    for (int g = 0; g < 4; g++)
        aBb[g] = sb + 1024 + 16384 + swa(n0 + g * 16 + lrow, lqh);

    float acc[2][8][4];
#pragma unroll
    for (int mt = 0; mt < 2; mt++)
#pragma unroll
        for (int nt = 0; nt < 8; nt++)
#pragma unroll
            for (int j = 0; j < 4; j++) acc[mt][nt][j] = 0.0f;

    // global load staging regs
    float4 sA[4];
    uint4  sBh[2], sBl[2];

    auto GLOAD = [&](int c) {
        const int k0 = c * 32;
#pragma unroll
        for (int i = 0; i < 4; i++) {
            int fid = i * 256 + tid;
            int r = fid >> 3, cq = fid & 7;
            sA[i] = *(const float4*)(Ap + (size_t)(bm + r) * K + k0 + cq * 4);
        }
#pragma unroll
        for (int i = 0; i < 2; i++) {
            int fid = i * 256 + tid;
            int r = fid >> 2, c16 = fid & 3;
            size_t go = (size_t)(bn + r) * K + k0 + c16 * 8;
            sBh[i] = *(const uint4*)(BH + go);
            sBl[i] = *(const uint4*)(BL + go);
        }
    };
    auto SSTORE = [&](int b) {
        char* s = smem + 1024 + b * 32768;
#pragma unroll
        for (int i = 0; i < 4; i++) {
            float4 v = sA[i];
            float h0 = bfr(v.x), h1 = bfr(v.y), h2 = bfr(v.z), h3 = bfr(v.w);
            uint2 H = make_uint2(pack2bf(h0, h1), pack2bf(h2, h3));
            uint2 L = make_uint2(pack2bf(v.x - h0, v.y - h1),
                                 pack2bf(v.z - h2, v.w - h3));
            int fid = i * 256 + tid;
            int r = fid >> 3, cq = fid & 7;
            uint32_t ad = swa(r, cq >> 1) + (cq & 1) * 8;
            *(uint2*)(s + ad)        = H;
            *(uint2*)(s + 8192 + ad) = L;
        }
#pragma unroll
        for (int i = 0; i < 2; i++) {
            int fid = i * 256 + tid;
            int r = fid >> 2, c16 = fid & 3;
            uint32_t ad = swa(r, c16);
            *(uint4*)(s + 16384 + ad) = sBh[i];
            *(uint4*)(s + 24576 + ad) = sBl[i];
        }
    };

    const int NC = K / 32;
    GLOAD(0);
    SSTORE(0);
    __syncthreads();

    for (int c = 0; c < NC; c++) {
        if (c + 1 < NC) GLOAD(c + 1);

        const uint32_t boff = (uint32_t)(c & 1) * 32768u;
#pragma unroll
        for (int ks = 0; ks < 2; ks++) {
            const uint32_t kx = (uint32_t)ks << 5;   // toggles 16B-chunk bit1
            uint32_t ah[2][4], al[2][4], bh[4][4], bl[4][4];
#pragma unroll
            for (int mt = 0; mt < 2; mt++) {
                uint32_t ad = (aAb[mt] + boff) ^ kx;
                ldsm4(ah[mt], ad);
                ldsm4(al[mt], ad + 8192);
            }
#pragma unroll
            for (int g = 0; g < 4; g++) {
                uint32_t ad = (aBb[g] + boff) ^ kx;
                ldsm4(bh[g], ad);
                ldsm4(bl[g], ad + 8192);
            }
#pragma unroll
            for (int mt = 0; mt < 2; mt++)
#pragma unroll
                for (int g = 0; g < 4; g++)
#pragma unroll
                    for (int h = 0; h < 2; h++) {
                        const int nt = g * 2 + h;
                        mma_bf16(acc[mt][nt], ah[mt], bh[g][h], bh[g][h + 2]);
                        mma_bf16(acc[mt][nt], ah[mt], bl[g][h], bl[g][h + 2]);
                        mma_bf16(acc[mt][nt], al[mt], bh[g][h], bh[g][h + 2]);
                    }
        }
        if (c + 1 < NC) SSTORE((c + 1) & 1);
        __syncthreads();
    }

    // ---- epilogue: bias + optional relu, float2 stores ----
    const float* bias = (const float*)smem;
#pragma unroll
    for (int mt = 0; mt < 2; mt++) {
        const int mrow = bm + m0 + mt * 16 + (lane >> 2);
#pragma unroll
        for (int nt = 0; nt < 8; nt++) {
            const int nc = n0 + nt * 8 + 2 * (lane & 3);
            const float b0 = bias[nc], b1 = bias[nc + 1];
            float o0 = acc[mt][nt][0] + b0;
            float o1 = acc[mt][nt][1] + b1;
            float o2 = acc[mt][nt][2] + b0;
            float o3 = acc[mt][nt][3] + b1;
            if (RELU) {
                o0 = fmaxf(o0, 0.f); o1 = fmaxf(o1, 0.f);
                o2 = fmaxf(o2, 0.f); o3 = fmaxf(o3, 0.f);
            }
            *(float2*)(Cp + (size_t)mrow * N + bn + nc)       = make_float2(o0, o1);
            *(float2*)(Cp + (size_t)(mrow + 8) * N + bn + nc) = make_float2(o2, o3);
        }
    }
}

// ---------------------------------------------------------------------------
extern "C" void kernel_launch(void* const* d_in, const int* in_sizes, int n_in,
                              void* d_out, int out_size)
{
    const float* inputs = (const float*)d_in[0];
    const int*   sel_s  = (const int*)d_in[1];
    const int*   sel_d  = (const int*)d_in[2];
    const float* Ws1 = (const float*)d_in[3];
    const float* bs1 = (const float*)d_in[4];
    const float* Ws2 = (const float*)d_in[5];
    const float* bs2 = (const float*)d_in[6];
    const float* Wd1 = (const float*)d_in[7];
    const float* bd1 = (const float*)d_in[8];
    const float* Wd2 = (const float*)d_in[9];
    const float* bd2 = (const float*)d_in[10];
    float* out = (float*)d_out;

    void* p;
    float *y1, *y2, *y3;
    cudaGetSymbolAddress(&p, g_y1); y1 = (float*)p;
    cudaGetSymbolAddress(&p, g_y2); y2 = (float*)p;
    cudaGetSymbolAddress(&p, g_y3); y3 = (float*)p;
    bf16 *w1h, *w1l, *w2h, *w2l, *w3h, *w3l, *w4h, *w4l;
    cudaGetSymbolAddress(&p, g_w1h); w1h = (bf16*)p;
    cudaGetSymbolAddress(&p, g_w1l); w1l = (bf16*)p;
    cudaGetSymbolAddress(&p, g_w2h); w2h = (bf16*)p;
    cudaGetSymbolAddress(&p, g_w2l); w2l = (bf16*)p;
    cudaGetSymbolAddress(&p, g_w3h); w3h = (bf16*)p;
    cudaGetSymbolAddress(&p, g_w3l); w3l = (bf16*)p;
    cudaGetSymbolAddress(&p, g_w4h); w4h = (bf16*)p;
    cudaGetSymbolAddress(&p, g_w4l); w4l = (bf16*)p;

    const int SMEM_BYTES = 1024 + 2 * 32768;   // 66560
    cudaFuncSetAttribute(gemm_mma_kernel<256, 512, true>,
                         cudaFuncAttributeMaxDynamicSharedMemorySize, SMEM_BYTES);
    cudaFuncSetAttribute(gemm_mma_kernel<512, 256, true>,
                         cudaFuncAttributeMaxDynamicSharedMemorySize, SMEM_BYTES);
    cudaFuncSetAttribute(gemm_mma_kernel<512, 128, false>,
                         cudaFuncAttributeMaxDynamicSharedMemorySize, SMEM_BYTES);

    dim3 tb(32, 8);
    // weight prepass (transpose + bf16 hi/lo split)
    wprep_kernel<256, 512><<<dim3(8, 16, 8), tb>>>(Ws1, sel_s, w1h, w1l);
    wprep_kernel<512, 256><<<dim3(16, 8, 8), tb>>>(Ws2, sel_s, w2h, w2l);
    wprep_kernel<256, 512><<<dim3(8, 16, 8), tb>>>(Wd1, sel_d, w3h, w3l);
    wprep_kernel<512, 128><<<dim3(16, 4, 8), tb>>>(Wd2, sel_d, w4h, w4l);

    dim3 blk(256);
    gemm_mma_kernel<256, 512, true ><<<dim3(4, 16, 8), blk, SMEM_BYTES>>>(inputs, w1h, w1l, bs1, y1, sel_s);
    gemm_mma_kernel<512, 256, true ><<<dim3(2, 16, 8), blk, SMEM_BYTES>>>(y1, w2h, w2l, bs2, y2, sel_s);
    gemm_mma_kernel<256, 512, true ><<<dim3(4, 16, 8), blk, SMEM_BYTES>>>(y2, w3h, w3l, bd1, y3, sel_d);
    gemm_mma_kernel<512, 128, false><<<dim3(1, 16, 8), blk, SMEM_BYTES>>>(y3, w4h, w4l, bd2, out, sel_d);
}

// round 5
// speedup vs baseline: 2.7298x; 1.3106x over previous
#include <cuda_runtime.h>
#include <cuda_bf16.h>
#include <cstdint>

// ---------------------------------------------------------------------------
// MADPSNet via mma.sync bf16 (3-pass hi/lo error-compensated) GEMMs, v2.
//   - one fused prepass: split input + 4 selected weight mats to bf16 hi/lo
//   - GEMM mainloop: all-cp.async 3-stage pipeline, B loaded [K,N] with
//     ldmatrix.trans (no weight transpose needed)
//   - intermediates stored as bf16 hi/lo pairs directly from the epilogue
//
//   L1: y1 = relu(in @ Ws1[e_s] + bs1)   [2048,256]x[256,512]
//   L2: y2 = relu(y1 @ Ws2[e_s] + bs2)   [2048,512]x[512,256]
//   L3: y3 = relu(y2 @ Wd1[e_d] + bd1)   [2048,256]x[256,512]
//   L4: out =      y3 @ Wd2[e_d] + bd2   [2048,512]x[512,128]
// ---------------------------------------------------------------------------

#define NUM_AGENTS 8
#define BATCH      2048
typedef __nv_bfloat16 bf16;

// ---------------- scratch (__device__ globals) ----------------------------
__device__ bf16 g_inh[NUM_AGENTS * BATCH * 256];
__device__ bf16 g_inl[NUM_AGENTS * BATCH * 256];
__device__ bf16 g_y1h[NUM_AGENTS * BATCH * 512];
__device__ bf16 g_y1l[NUM_AGENTS * BATCH * 512];
__device__ bf16 g_y2h[NUM_AGENTS * BATCH * 256];
__device__ bf16 g_y2l[NUM_AGENTS * BATCH * 256];
__device__ bf16 g_y3h[NUM_AGENTS * BATCH * 512];
__device__ bf16 g_y3l[NUM_AGENTS * BATCH * 512];

__device__ bf16 g_w1h[NUM_AGENTS * 256 * 512];
__device__ bf16 g_w1l[NUM_AGENTS * 256 * 512];
__device__ bf16 g_w2h[NUM_AGENTS * 512 * 256];
__device__ bf16 g_w2l[NUM_AGENTS * 512 * 256];
__device__ bf16 g_w3h[NUM_AGENTS * 256 * 512];
__device__ bf16 g_w3l[NUM_AGENTS * 256 * 512];
__device__ bf16 g_w4h[NUM_AGENTS * 512 * 128];
__device__ bf16 g_w4l[NUM_AGENTS * 512 * 128];

// ---------------- helpers --------------------------------------------------
__device__ __forceinline__ uint32_t smem_u32(const void* p) {
    uint32_t a;
    asm("{ .reg .u64 t; cvta.to.shared.u64 t, %1; cvt.u32.u64 %0, t; }" : "=r"(a) : "l"(p));
    return a;
}
__device__ __forceinline__ void ldsm4(uint32_t (&r)[4], uint32_t addr) {
    asm volatile("ldmatrix.sync.aligned.m8n8.x4.shared.b16 {%0,%1,%2,%3}, [%4];"
                 : "=r"(r[0]), "=r"(r[1]), "=r"(r[2]), "=r"(r[3]) : "r"(addr));
}
__device__ __forceinline__ void ldsm4t(uint32_t (&r)[4], uint32_t addr) {
    asm volatile("ldmatrix.sync.aligned.m8n8.x4.trans.shared.b16 {%0,%1,%2,%3}, [%4];"
                 : "=r"(r[0]), "=r"(r[1]), "=r"(r[2]), "=r"(r[3]) : "r"(addr));
}
__device__ __forceinline__ void mma_bf16(float (&d)[4], const uint32_t (&a)[4],
                                         uint32_t b0, uint32_t b1) {
    asm volatile(
        "mma.sync.aligned.m16n8k16.row.col.f32.bf16.bf16.f32 "
        "{%0,%1,%2,%3}, {%4,%5,%6,%7}, {%8,%9}, {%0,%1,%2,%3};"
        : "+f"(d[0]), "+f"(d[1]), "+f"(d[2]), "+f"(d[3])
        : "r"(a[0]), "r"(a[1]), "r"(a[2]), "r"(a[3]), "r"(b0), "r"(b1));
}
__device__ __forceinline__ void cp16(uint32_t dst, const void* src) {
    asm volatile("cp.async.cg.shared.global [%0], [%1], 16;" :: "r"(dst), "l"(src));
}
template <int NW>
__device__ __forceinline__ void cp_wait() {
    asm volatile("cp.async.wait_group %0;" :: "n"(NW));
}
#define CP_COMMIT() asm volatile("cp.async.commit_group;" ::: "memory")

__device__ __forceinline__ float bfr(float x) {
    return __bfloat162float(__float2bfloat16_rn(x));
}
__device__ __forceinline__ uint32_t pack2bf(float a, float b) {
    __nv_bfloat162 t = __floats2bfloat162_rn(a, b);
    return *reinterpret_cast<uint32_t*>(&t);
}
// A-tile swizzle: 128 rows x 32 bf16 (64B rows); 16B chunk c16 in [0,4)
__device__ __forceinline__ uint32_t swa(int row, int c16) {
    return (uint32_t)(row * 64 + (((c16) ^ ((row >> 1) & 3)) << 4));
}

// ---------------- fused prepass: elementwise bf16 hi/lo splits -------------
// seg 0..3: selected weight mats; seg 4: raw input. grid (32, 5, 8), 256 thr.
__global__ void __launch_bounds__(256)
prep_kernel(const float* __restrict__ Ws1, const float* __restrict__ Ws2,
            const float* __restrict__ Wd1, const float* __restrict__ Wd2,
            const float* __restrict__ inputs,
            const int* __restrict__ sel_s, const int* __restrict__ sel_d,
            bf16* __restrict__ w1h, bf16* __restrict__ w1l,
            bf16* __restrict__ w2h, bf16* __restrict__ w2l,
            bf16* __restrict__ w3h, bf16* __restrict__ w3l,
            bf16* __restrict__ w4h, bf16* __restrict__ w4l,
            bf16* __restrict__ inh, bf16* __restrict__ inl)
{
    const int seg = blockIdx.y;
    const int ag  = blockIdx.z;
    const float* src;
    bf16 *oh, *ol;
    int n4;   // float4 count per agent
    int e;
    switch (seg) {
    case 0:
        e = sel_s[ag]; e = e < 0 ? 0 : (e > 7 ? 7 : e);
        src = Ws1 + (size_t)e * 131072; oh = w1h + (size_t)ag * 131072;
        ol = w1l + (size_t)ag * 131072; n4 = 32768; break;
    case 1:
        e = sel_s[ag]; e = e < 0 ? 0 : (e > 7 ? 7 : e);
        src = Ws2 + (size_t)e * 131072; oh = w2h + (size_t)ag * 131072;
        ol = w2l + (size_t)ag * 131072; n4 = 32768; break;
    case 2:
        e = sel_d[ag]; e = e < 0 ? 0 : (e > 7 ? 7 : e);
        src = Wd1 + (size_t)e * 131072; oh = w3h + (size_t)ag * 131072;
        ol = w3l + (size_t)ag * 131072; n4 = 32768; break;
    case 3:
        e = sel_d[ag]; e = e < 0 ? 0 : (e > 7 ? 7 : e);
        src = Wd2 + (size_t)e * 65536;  oh = w4h + (size_t)ag * 65536;
        ol = w4l + (size_t)ag * 65536;  n4 = 16384; break;
    default:
        src = inputs + (size_t)ag * 524288; oh = inh + (size_t)ag * 524288;
        ol = inl + (size_t)ag * 524288; n4 = 131072; break;
    }
    for (int i = blockIdx.x * 256 + threadIdx.x; i < n4; i += 32 * 256) {
        float4 v = ((const float4*)src)[i];
        float h0 = bfr(v.x), h1 = bfr(v.y), h2 = bfr(v.z), h3 = bfr(v.w);
        ((uint2*)oh)[i] = make_uint2(pack2bf(h0, h1), pack2bf(h2, h3));
        ((uint2*)ol)[i] = make_uint2(pack2bf(v.x - h0, v.y - h1),
                                     pack2bf(v.z - h2, v.w - h3));
    }
}

// ---------------- main GEMM ------------------------------------------------
// C[ag] = act(A[ag] @ W[ag] + b[sel[ag]])
//   A hi/lo: [ag, BATCH, K] bf16 row-major     (ldmatrix, row operand)
//   W hi/lo: [ag, K, N]    bf16 row-major     (ldmatrix.trans, col operand)
// CTA: 128x128 tile, 256 thr (8 warps, 4x2; warp tile 32m x 64n), BK=32,
// 3-stage cp.async pipeline. Stage = Ah|Al|Bh|Bl, 8KB each (32KB).
// SPLIT: write Oh/Ol bf16 pairs; else fp32 Out.
template <int K, int N, bool RELU, bool SPLIT>
__global__ void __launch_bounds__(256, 2)
gemm_mma_kernel(const bf16* __restrict__ AH, const bf16* __restrict__ AL,
                const bf16* __restrict__ WH, const bf16* __restrict__ WL,
                const float* __restrict__ Ball,
                float* __restrict__ Out,
                bf16* __restrict__ Oh, bf16* __restrict__ Ol,
                const int* __restrict__ sel)
{
    extern __shared__ __align__(1024) char smem[];
    const uint32_t sb = smem_u32(smem);

    const int tid  = threadIdx.x;
    const int wid  = tid >> 5;
    const int lane = tid & 31;

    const int ag = blockIdx.z;
    int e = sel[ag]; e = e < 0 ? 0 : (e > 7 ? 7 : e);

    const bf16* Ah_ = AH + (size_t)ag * BATCH * K;
    const bf16* Al_ = AL + (size_t)ag * BATCH * K;
    const bf16* Bh_ = WH + (size_t)ag * K * N;
    const bf16* Bl_ = WL + (size_t)ag * K * N;
    const float* bp = Ball + (size_t)e * N;

    const int bm = blockIdx.y * 128;
    const int bn = blockIdx.x * 128;

    // smem: [0..512) bias fp32, [1024..) 3 x 32KB stage buffers
    if (tid < 128) ((float*)smem)[tid] = bp[bn + tid];

    const int m0 = (wid >> 1) * 32;
    const int n0 = (wid & 1) * 64;

    // ---- precomputed ldmatrix addresses (stage 0) ----
    const int lrow = lane & 15, lqh = lane >> 4;
    uint32_t aA[2];
#pragma unroll
    for (int mt = 0; mt < 2; mt++)
        aA[mt] = sb + 1024 + swa(m0 + mt * 16 + lrow, lqh);
    // B (trans): lane -> (krow, n-chunk); 4 groups of 16 n
    const int kr  = (lane & 7) + ((lane >> 3) & 1) * 8;
    uint32_t bB[4];
#pragma unroll
    for (int g = 0; g < 4; g++) {
        int nch = ((n0 + g * 16) >> 3) + (lane >> 4);
        bB[g] = sb + 1024 + 16384 + kr * 256 + ((uint32_t)(nch ^ (kr & 7)) << 4);
    }

    float acc[2][8][4];
#pragma unroll
    for (int mt = 0; mt < 2; mt++)
#pragma unroll
        for (int nt = 0; nt < 8; nt++)
#pragma unroll
            for (int j = 0; j < 4; j++) acc[mt][nt][j] = 0.0f;

    const int NC = K / 32;

    auto ISSUE = [&](int c) {
        const int k0 = c * 32;
        const uint32_t s = sb + 1024 + (uint32_t)(c % 3) * 32768u;
        // A: 128 rows x 4 chunks(16B); 512 chunks, 2/thread (h and l)
#pragma unroll
        for (int i = 0; i < 2; i++) {
            int fid = i * 256 + tid;
            int r = fid >> 2, cq = fid & 3;
            size_t go = (size_t)(bm + r) * K + k0 + cq * 8;
            uint32_t ad = swa(r, cq);
            cp16(s + ad,        Ah_ + go);
            cp16(s + 8192 + ad, Al_ + go);
        }
        // B: 32 k-rows x 16 chunks(16B) = 512, 2/thread
#pragma unroll
        for (int i = 0; i < 2; i++) {
            int fid = i * 256 + tid;
            int r = fid >> 4, cq = fid & 15;
            size_t go = (size_t)(k0 + r) * N + bn + cq * 8;
            uint32_t ad = (uint32_t)(r * 256 + ((cq ^ (r & 7)) << 4));
            cp16(s + 16384 + ad, Bh_ + go);
            cp16(s + 24576 + ad, Bl_ + go);
        }
        CP_COMMIT();
    };

    ISSUE(0);
    ISSUE(1);

#pragma unroll 3
    for (int c = 0; c < NC; c++) {
        if (c + 1 < NC) cp_wait<1>(); else cp_wait<0>();
        __syncthreads();
        if (c + 2 < NC) ISSUE(c + 2);

        const uint32_t stg = (uint32_t)(c % 3) * 32768u;
#pragma unroll
        for (int ks = 0; ks < 2; ks++) {
            uint32_t ah[2][4], al[2][4];
#pragma unroll
            for (int mt = 0; mt < 2; mt++) {
                uint32_t ad = (aA[mt] + stg) ^ ((uint32_t)ks << 5);
                ldsm4(ah[mt], ad);
                ldsm4(al[mt], ad + 8192);
            }
#pragma unroll
            for (int g = 0; g < 4; g++) {
                uint32_t bh[4], bl[4];
                uint32_t bd = bB[g] + stg + (uint32_t)ks * 4096u;
                ldsm4t(bh, bd);
                ldsm4t(bl, bd + 8192);
#pragma unroll
                for (int mt = 0; mt < 2; mt++) {
                    mma_bf16(acc[mt][2 * g],     ah[mt], bh[0], bh[1]);
                    mma_bf16(acc[mt][2 * g],     ah[mt], bl[0], bl[1]);
                    mma_bf16(acc[mt][2 * g],     al[mt], bh[0], bh[1]);
                    mma_bf16(acc[mt][2 * g + 1], ah[mt], bh[2], bh[3]);
                    mma_bf16(acc[mt][2 * g + 1], ah[mt], bl[2], bl[3]);
                    mma_bf16(acc[mt][2 * g + 1], al[mt], bh[2], bh[3]);
                }
            }
        }
    }

    // ---- epilogue ----
    const float* bias = (const float*)smem;
    float* Cp = SPLIT ? nullptr : (Out + (size_t)ag * BATCH * N);
    bf16* OhP = SPLIT ? (Oh + (size_t)ag * BATCH * N) : nullptr;
    bf16* OlP = SPLIT ? (Ol + (size_t)ag * BATCH * N) : nullptr;

#pragma unroll
    for (int mt = 0; mt < 2; mt++) {
        const int mrow = bm + m0 + mt * 16 + (lane >> 2);
#pragma unroll
        for (int nt = 0; nt < 8; nt++) {
            const int nc = n0 + nt * 8 + 2 * (lane & 3);
            const float b0 = bias[nc], b1 = bias[nc + 1];
            float o0 = acc[mt][nt][0] + b0;
            float o1 = acc[mt][nt][1] + b1;
            float o2 = acc[mt][nt][2] + b0;
            float o3 = acc[mt][nt][3] + b1;
            if (RELU) {
                o0 = fmaxf(o0, 0.f); o1 = fmaxf(o1, 0.f);
                o2 = fmaxf(o2, 0.f); o3 = fmaxf(o3, 0.f);
            }
            if (SPLIT) {
                float h0 = bfr(o0), h1 = bfr(o1), h2 = bfr(o2), h3 = bfr(o3);
                size_t i0 = (size_t)mrow * N + bn + nc;
                size_t i1 = (size_t)(mrow + 8) * N + bn + nc;
                *(uint32_t*)(OhP + i0) = pack2bf(h0, h1);
                *(uint32_t*)(OlP + i0) = pack2bf(o0 - h0, o1 - h1);
                *(uint32_t*)(OhP + i1) = pack2bf(h2, h3);
                *(uint32_t*)(OlP + i1) = pack2bf(o2 - h2, o3 - h3);
            } else {
                *(float2*)(Cp + (size_t)mrow * N + bn + nc)       = make_float2(o0, o1);
                *(float2*)(Cp + (size_t)(mrow + 8) * N + bn + nc) = make_float2(o2, o3);
            }
        }
    }
}

// ---------------------------------------------------------------------------
extern "C" void kernel_launch(void* const* d_in, const int* in_sizes, int n_in,
                              void* d_out, int out_size)
{
    const float* inputs = (const float*)d_in[0];
    const int*   sel_s  = (const int*)d_in[1];
    const int*   sel_d  = (const int*)d_in[2];
    const float* Ws1 = (const float*)d_in[3];
    const float* bs1 = (const float*)d_in[4];
    const float* Ws2 = (const float*)d_in[5];
    const float* bs2 = (const float*)d_in[6];
    const float* Wd1 = (const float*)d_in[7];
    const float* bd1 = (const float*)d_in[8];
    const float* Wd2 = (const float*)d_in[9];
    const float* bd2 = (const float*)d_in[10];
    float* out = (float*)d_out;

    void* p;
    bf16 *inh, *inl, *y1h, *y1l, *y2h, *y2l, *y3h, *y3l;
    cudaGetSymbolAddress(&p, g_inh); inh = (bf16*)p;
    cudaGetSymbolAddress(&p, g_inl); inl = (bf16*)p;
    cudaGetSymbolAddress(&p, g_y1h); y1h = (bf16*)p;
    cudaGetSymbolAddress(&p, g_y1l); y1l = (bf16*)p;
    cudaGetSymbolAddress(&p, g_y2h); y2h = (bf16*)p;
    cudaGetSymbolAddress(&p, g_y2l); y2l = (bf16*)p;
    cudaGetSymbolAddress(&p, g_y3h); y3h = (bf16*)p;
    cudaGetSymbolAddress(&p, g_y3l); y3l = (bf16*)p;
    bf16 *w1h, *w1l, *w2h, *w2l, *w3h, *w3l, *w4h, *w4l;
    cudaGetSymbolAddress(&p, g_w1h); w1h = (bf16*)p;
    cudaGetSymbolAddress(&p, g_w1l); w1l = (bf16*)p;
    cudaGetSymbolAddress(&p, g_w2h); w2h = (bf16*)p;
    cudaGetSymbolAddress(&p, g_w2l); w2l = (bf16*)p;
    cudaGetSymbolAddress(&p, g_w3h); w3h = (bf16*)p;
    cudaGetSymbolAddress(&p, g_w3l); w3l = (bf16*)p;
    cudaGetSymbolAddress(&p, g_w4h); w4h = (bf16*)p;
    cudaGetSymbolAddress(&p, g_w4l); w4l = (bf16*)p;

    const int SMEM_BYTES = 1024 + 3 * 32768;   // 99328
    cudaFuncSetAttribute(gemm_mma_kernel<256, 512, true,  true >,
                         cudaFuncAttributeMaxDynamicSharedMemorySize, SMEM_BYTES);
    cudaFuncSetAttribute(gemm_mma_kernel<512, 256, true,  true >,
                         cudaFuncAttributeMaxDynamicSharedMemorySize, SMEM_BYTES);
    cudaFuncSetAttribute(gemm_mma_kernel<512, 128, false, false>,
                         cudaFuncAttributeMaxDynamicSharedMemorySize, SMEM_BYTES);

    // fused prepass: all weight splits + input split in one launch
    prep_kernel<<<dim3(32, 5, 8), 256>>>(Ws1, Ws2, Wd1, Wd2, inputs, sel_s, sel_d,
                                         w1h, w1l, w2h, w2l, w3h, w3l, w4h, w4l,
                                         inh, inl);

    dim3 blk(256);
    gemm_mma_kernel<256, 512, true,  true ><<<dim3(4, 16, 8), blk, SMEM_BYTES>>>(
        inh, inl, w1h, w1l, bs1, nullptr, y1h, y1l, sel_s);
    gemm_mma_kernel<512, 256, true,  true ><<<dim3(2, 16, 8), blk, SMEM_BYTES>>>(
        y1h, y1l, w2h, w2l, bs2, nullptr, y2h, y2l, sel_s);
    gemm_mma_kernel<256, 512, true,  true ><<<dim3(4, 16, 8), blk, SMEM_BYTES>>>(
        y2h, y2l, w3h, w3l, bd1, nullptr, y3h, y3l, sel_d);
    gemm_mma_kernel<512, 128, false, false><<<dim3(1, 16, 8), blk, SMEM_BYTES>>>(
        y3h, y3l, w4h, w4l, bd2, out, nullptr, nullptr, sel_d);
}